// round 11
// baseline (speedup 1.0000x reference)
#include <cuda_runtime.h>

#define C_CH   256
#define K_KERN 4
#define HID    64
#define HW     4096
#define B_MAX  32
#define S_STRIDE 68

__device__ float g_gap[B_MAX * C_CH];
__device__ float g_attn[B_MAX * K_KERN];
__device__ int   g_cnt[B_MAX];
__device__ int   g_flag[B_MAX];

// ---------------------------------------------------------------------------
// Init: zero per-batch counters/flags (replay-safe).
// ---------------------------------------------------------------------------
__global__ void init_kernel() {
    if (threadIdx.x < B_MAX) {
        g_cnt[threadIdx.x] = 0;
        g_flag[threadIdx.x] = 0;
    }
}

// ---------------------------------------------------------------------------
// Fused kernel: one block per (b,c) plane.
//  Phase 1: stage plane to smem + plane mean -> g_gap[bc]; last-arriving
//           block of batch b computes attn inline and releases flag[b].
//  Phase 2: spin on flag[b] (acquire), conv from smem, streaming stores.
// x is read from DRAM exactly once. Total DRAM = 268MB (read x + write out).
// ---------------------------------------------------------------------------
__global__ void __launch_bounds__(256) fused_kernel(const float* __restrict__ x,
                                                    const float* __restrict__ conv_w,
                                                    const float* __restrict__ fc1_w,
                                                    const float* __restrict__ fc1_b,
                                                    const float* __restrict__ fc2_w,
                                                    const float* __restrict__ fc2_b,
                                                    float* __restrict__ out) {
    const int bc = blockIdx.x;
    const int b = bc >> 8;
    const int c = bc & 255;
    const int tid = threadIdx.x;

    __shared__ float s[66 * S_STRIDE];
    __shared__ float sh_red[8];
    __shared__ int   sh_last;
    __shared__ float sh_g[C_CH];
    __shared__ float sh_h[HID];
    __shared__ float sh_lg[K_KERN];

    // ---- zero halo (260 border cells) ----
    for (int i = tid; i < 260; i += 256) {
        int idx;
        if (i < 66)        idx = i;
        else if (i < 132)  idx = 65 * S_STRIDE + (i - 66);
        else if (i < 196)  idx = (i - 132 + 1) * S_STRIDE;
        else               idx = (i - 196 + 1) * S_STRIDE + 65;
        s[idx] = 0.f;
    }

    // ---- stage plane into smem interior, summing en route ----
    const float4* __restrict__ xp = (const float4*)(x + (size_t)bc * HW);
    float sum = 0.f;
#pragma unroll
    for (int i = 0; i < 4; i++) {
        const int idx = tid + i * 256;       // 0..1023 float4s
        const int row = idx >> 4;
        const int c4  = idx & 15;
        float4 v = __ldg(&xp[idx]);
        sum += (v.x + v.y) + (v.z + v.w);
        float* d = &s[(row + 1) * S_STRIDE + 1 + c4 * 4];
        d[0] = v.x; d[1] = v.y; d[2] = v.z; d[3] = v.w;
    }

    // ---- block reduce plane sum ----
#pragma unroll
    for (int o = 16; o > 0; o >>= 1) sum += __shfl_down_sync(0xffffffffu, sum, o);
    const int lane = tid & 31, wrp = tid >> 5;
    if (lane == 0) sh_red[wrp] = sum;
    __syncthreads();
    if (tid == 0) {
        float t = 0.f;
#pragma unroll
        for (int i = 0; i < 8; i++) t += sh_red[i];
        g_gap[bc] = t * (1.0f / (float)HW);
        __threadfence();
        int old = atomicAdd(&g_cnt[b], 1);
        sh_last = (old == C_CH - 1);
        if (sh_last) __threadfence();        // acquire all writers' g_gap stores
    }
    __syncthreads();

    // ---- last-arriving block computes attention for batch b ----
    if (sh_last) {
        sh_g[tid] = g_gap[b * C_CH + tid];
        __syncthreads();
        if (tid < HID) {
            const float* __restrict__ wr = fc1_w + tid * C_CH;
            float acc = fc1_b[tid];
#pragma unroll 8
            for (int cc = 0; cc < C_CH; cc++) acc = fmaf(sh_g[cc], wr[cc], acc);
            sh_h[tid] = fmaxf(acc, 0.f);
        }
        __syncthreads();
        if (tid < K_KERN) {
            const float* __restrict__ wr = fc2_w + tid * HID;
            float acc = fc2_b[tid];
#pragma unroll 8
            for (int j = 0; j < HID; j++) acc = fmaf(sh_h[j], wr[j], acc);
            sh_lg[tid] = acc;
        }
        __syncthreads();
        if (tid == 0) {
            float m = sh_lg[0];
#pragma unroll
            for (int k = 1; k < K_KERN; k++) m = fmaxf(m, sh_lg[k]);
            float e[K_KERN], ssum = 0.f;
#pragma unroll
            for (int k = 0; k < K_KERN; k++) { e[k] = expf(sh_lg[k] - m); ssum += e[k]; }
            const float inv = 1.0f / ssum;
#pragma unroll
            for (int k = 0; k < K_KERN; k++) g_attn[b * K_KERN + k] = e[k] * inv;
            __threadfence();
            // release flag
            asm volatile("st.global.release.gpu.b32 [%0], %1;" :: "l"(&g_flag[b]), "r"(1));
        }
    }

    // ---- spin until attn[b] ready (thread 0 only), then broadcast ----
    if (tid == 0) {
        int f;
        while (true) {
            asm volatile("ld.global.acquire.gpu.b32 %0, [%1];" : "=r"(f) : "l"(&g_flag[b]));
            if (f) break;
            __nanosleep(64);
        }
    }
    __syncthreads();

    // ---- effective 9-tap filter ----
    const float a0 = g_attn[b * 4 + 0];
    const float a1 = g_attn[b * 4 + 1];
    const float a2 = g_attn[b * 4 + 2];
    const float a3 = g_attn[b * 4 + 3];
    float w[9];
    const float* __restrict__ w0 = conv_w + (size_t)0 * C_CH * 9 + c * 9;
    const float* __restrict__ w1 = conv_w + (size_t)1 * C_CH * 9 + c * 9;
    const float* __restrict__ w2 = conv_w + (size_t)2 * C_CH * 9 + c * 9;
    const float* __restrict__ w3 = conv_w + (size_t)3 * C_CH * 9 + c * 9;
#pragma unroll
    for (int i = 0; i < 9; i++)
        w[i] = fmaf(a0, __ldg(&w0[i]),
               fmaf(a1, __ldg(&w1[i]),
               fmaf(a2, __ldg(&w2[i]), a3 * __ldg(&w3[i]))));

    // ---- conv from smem: 4x4 register sliding window per thread ----
    const int tx = tid & 15;
    const int ty = tid >> 4;
    const int oc = tx * 4;
    const int orow = ty * 4;

    float rb[3][6];
#pragma unroll
    for (int r = 0; r < 3; r++) {
        const float* sp = &s[(orow + r) * S_STRIDE + oc];
        float4 v = *(const float4*)sp;
        rb[r][0] = v.x; rb[r][1] = v.y; rb[r][2] = v.z; rb[r][3] = v.w;
        rb[r][4] = sp[4]; rb[r][5] = sp[5];
    }

    float* __restrict__ op = out + (size_t)bc * HW;
#pragma unroll
    for (int rr = 0; rr < 4; rr++) {
        float4 o;
        float* ov = (float*)&o;
#pragma unroll
        for (int i = 0; i < 4; i++) {
            float acc;
            acc = rb[0][i] * w[0];
            acc = fmaf(rb[0][i + 1], w[1], acc);
            acc = fmaf(rb[0][i + 2], w[2], acc);
            acc = fmaf(rb[1][i],     w[3], acc);
            acc = fmaf(rb[1][i + 1], w[4], acc);
            acc = fmaf(rb[1][i + 2], w[5], acc);
            acc = fmaf(rb[2][i],     w[6], acc);
            acc = fmaf(rb[2][i + 1], w[7], acc);
            acc = fmaf(rb[2][i + 2], w[8], acc);
            ov[i] = acc;
        }
        __stcs((float4*)&op[(orow + rr) * 64 + oc], o);

        if (rr < 3) {
#pragma unroll
            for (int i = 0; i < 6; i++) { rb[0][i] = rb[1][i]; rb[1][i] = rb[2][i]; }
            const float* sp = &s[(orow + rr + 3) * S_STRIDE + oc];
            float4 v = *(const float4*)sp;
            rb[2][0] = v.x; rb[2][1] = v.y; rb[2][2] = v.z; rb[2][3] = v.w;
            rb[2][4] = sp[4]; rb[2][5] = sp[5];
        }
    }
}

// ---------------------------------------------------------------------------
extern "C" void kernel_launch(void* const* d_in, const int* in_sizes, int n_in,
                              void* d_out, int out_size) {
    const float* x      = (const float*)d_in[0];
    const float* conv_w = (const float*)d_in[1];
    const float* fc1_w  = (const float*)d_in[2];
    const float* fc1_b  = (const float*)d_in[3];
    const float* fc2_w  = (const float*)d_in[4];
    const float* fc2_b  = (const float*)d_in[5];
    float* out = (float*)d_out;

    const int B = in_sizes[0] / (C_CH * HW);   // 32

    init_kernel<<<1, 64>>>();
    fused_kernel<<<B * C_CH, 256>>>(x, conv_w, fc1_w, fc1_b, fc2_w, fc2_b, out);
}

// round 13
// speedup vs baseline: 2.3504x; 2.3504x over previous
#include <cuda_runtime.h>

#define C_CH   256
#define K_KERN 4
#define HID    64
#define HW     4096
#define B_MAX  32

__device__ float g_gap[B_MAX * C_CH];
__device__ float g_attn[B_MAX * K_KERN];

// ---------------------------------------------------------------------------
// Kernel 1: global average pool per (b,c) plane. One block per plane.
// (R5-proven form, unchanged.)
// ---------------------------------------------------------------------------
__global__ void __launch_bounds__(256) gap_kernel(const float* __restrict__ x) {
    const int bc = blockIdx.x;
    const float4* __restrict__ p = (const float4*)(x + (size_t)bc * HW);
    float s = 0.f;
#pragma unroll
    for (int i = 0; i < 4; i++) {
        float4 v = __ldg(&p[threadIdx.x + i * 256]);
        s += (v.x + v.y) + (v.z + v.w);
    }
#pragma unroll
    for (int o = 16; o > 0; o >>= 1) s += __shfl_down_sync(0xffffffffu, s, o);
    __shared__ float ws[8];
    const int lane = threadIdx.x & 31, w = threadIdx.x >> 5;
    if (lane == 0) ws[w] = s;
    __syncthreads();
    if (threadIdx.x == 0) {
        float t = 0.f;
#pragma unroll
        for (int i = 0; i < 8; i++) t += ws[i];
        g_gap[bc] = t * (1.0f / (float)HW);
    }
}

// ---------------------------------------------------------------------------
// Kernel 2: fc1 -> relu -> fc2 -> softmax. One block per batch. (unchanged)
// ---------------------------------------------------------------------------
__global__ void __launch_bounds__(256) attn_kernel(const float* __restrict__ fc1_w,
                                                   const float* __restrict__ fc1_b,
                                                   const float* __restrict__ fc2_w,
                                                   const float* __restrict__ fc2_b) {
    const int b = blockIdx.x;
    __shared__ float g[C_CH];
    __shared__ float h[HID];
    __shared__ float lg[K_KERN];

    g[threadIdx.x] = g_gap[b * C_CH + threadIdx.x];
    __syncthreads();

    if (threadIdx.x < HID) {
        const float* __restrict__ wr = fc1_w + threadIdx.x * C_CH;
        float acc = fc1_b[threadIdx.x];
#pragma unroll 8
        for (int c = 0; c < C_CH; c++) acc = fmaf(g[c], wr[c], acc);
        h[threadIdx.x] = fmaxf(acc, 0.f);
    }
    __syncthreads();

    if (threadIdx.x < K_KERN) {
        const float* __restrict__ wr = fc2_w + threadIdx.x * HID;
        float acc = fc2_b[threadIdx.x];
#pragma unroll 8
        for (int j = 0; j < HID; j++) acc = fmaf(h[j], wr[j], acc);
        lg[threadIdx.x] = acc;
    }
    __syncthreads();

    if (threadIdx.x == 0) {
        float m = lg[0];
#pragma unroll
        for (int k = 1; k < K_KERN; k++) m = fmaxf(m, lg[k]);
        float e[K_KERN], s = 0.f;
#pragma unroll
        for (int k = 0; k < K_KERN; k++) { e[k] = expf(lg[k] - m); s += e[k]; }
        const float inv = 1.0f / s;
#pragma unroll
        for (int k = 0; k < K_KERN; k++) g_attn[b * K_KERN + k] = e[k] * inv;
    }
}

// ---------------------------------------------------------------------------
// Kernel 3: depthwise 3x3, effective filter w_eff = sum_k attn[b,k]*w[k,c].
// v2: 256-bit loads (ld.global.nc.v8.b32), 8-lane octets span a 64-wide row.
// Horizontal halo via width-8 shuffles. Each octet streams a 4-row strip with
// a 3-row x 10-col register window. 32 octets per 256-thread block = 2 planes.
// 4 independent load streams per warp (2x the MLP of the 16-lane version).
// ---------------------------------------------------------------------------
__device__ __forceinline__ void ld_v8(const float* __restrict__ p, float* v) {
    unsigned r0, r1, r2, r3, r4, r5, r6, r7;
    asm volatile("ld.global.nc.v8.b32 {%0,%1,%2,%3,%4,%5,%6,%7}, [%8];"
                 : "=r"(r0), "=r"(r1), "=r"(r2), "=r"(r3),
                   "=r"(r4), "=r"(r5), "=r"(r6), "=r"(r7)
                 : "l"(p));
    v[0] = __uint_as_float(r0); v[1] = __uint_as_float(r1);
    v[2] = __uint_as_float(r2); v[3] = __uint_as_float(r3);
    v[4] = __uint_as_float(r4); v[5] = __uint_as_float(r5);
    v[6] = __uint_as_float(r6); v[7] = __uint_as_float(r7);
}

// Load one input row (10 floats incl. halo) for this octet.
__device__ __forceinline__ void load_row10(const float* __restrict__ xp,
                                           int row, int sub, float* d) {
    float v[8];
    if ((unsigned)row < 64u) {
        ld_v8(xp + row * 64 + sub * 8, v);
    } else {
#pragma unroll
        for (int i = 0; i < 8; i++) v[i] = 0.f;
    }
    float l = __shfl_up_sync(0xffffffffu, v[7], 1, 8);
    float r = __shfl_down_sync(0xffffffffu, v[0], 1, 8);
    if (sub == 0) l = 0.f;   // image left pad
    if (sub == 7) r = 0.f;   // image right pad
    d[0] = l;
#pragma unroll
    for (int i = 0; i < 8; i++) d[i + 1] = v[i];
    d[9] = r;
}

__global__ void __launch_bounds__(256) conv_kernel(const float* __restrict__ x,
                                                   const float* __restrict__ conv_w,
                                                   float* __restrict__ out) {
    const int tid  = threadIdx.x;
    const int lane = tid & 31;
    const int warp = tid >> 5;
    const int sub  = lane & 7;                 // col group: cols [sub*8, sub*8+8)
    const int oct  = warp * 4 + (lane >> 3);   // 0..31
    const int plane_local = oct >> 4;          // 0 or 1
    const int strip = oct & 15;                // 0..15 -> rows [strip*4, strip*4+4)

    const int pair = gridDim.x - 1 - blockIdx.x;   // reversed order
    const int bc = pair * 2 + plane_local;
    const int b = bc >> 8;
    const int c = bc & 255;

    const float a0 = g_attn[b * 4 + 0];
    const float a1 = g_attn[b * 4 + 1];
    const float a2 = g_attn[b * 4 + 2];
    const float a3 = g_attn[b * 4 + 3];
    float w[9];
    const float* __restrict__ w0 = conv_w + (size_t)0 * C_CH * 9 + c * 9;
    const float* __restrict__ w1 = conv_w + (size_t)1 * C_CH * 9 + c * 9;
    const float* __restrict__ w2 = conv_w + (size_t)2 * C_CH * 9 + c * 9;
    const float* __restrict__ w3 = conv_w + (size_t)3 * C_CH * 9 + c * 9;
#pragma unroll
    for (int i = 0; i < 9; i++)
        w[i] = fmaf(a0, __ldg(&w0[i]),
               fmaf(a1, __ldg(&w1[i]),
               fmaf(a2, __ldg(&w2[i]), a3 * __ldg(&w3[i]))));

    const float* __restrict__ xp = x + (size_t)bc * HW;
    float4* __restrict__ op = (float4*)(out + (size_t)bc * HW);

    const int rbase = strip * 4;

    float rb[3][10];
    load_row10(xp, rbase - 1, sub, rb[0]);
    load_row10(xp, rbase,     sub, rb[1]);

#pragma unroll
    for (int rr = 0; rr < 4; rr++) {
        const int i0 = rr % 3;
        const int i1 = (rr + 1) % 3;
        const int i2 = (rr + 2) % 3;
        load_row10(xp, rbase + rr + 1, sub, rb[i2]);

        float ov[8];
#pragma unroll
        for (int i = 0; i < 8; i++) {
            float acc;
            acc = rb[i0][i]     * w[0];
            acc = fmaf(rb[i0][i + 1], w[1], acc);
            acc = fmaf(rb[i0][i + 2], w[2], acc);
            acc = fmaf(rb[i1][i],     w[3], acc);
            acc = fmaf(rb[i1][i + 1], w[4], acc);
            acc = fmaf(rb[i1][i + 2], w[5], acc);
            acc = fmaf(rb[i2][i],     w[6], acc);
            acc = fmaf(rb[i2][i + 1], w[7], acc);
            acc = fmaf(rb[i2][i + 2], w[8], acc);
            ov[i] = acc;
        }
        float4 lo = make_float4(ov[0], ov[1], ov[2], ov[3]);
        float4 hi = make_float4(ov[4], ov[5], ov[6], ov[7]);
        __stcs(&op[(rbase + rr) * 16 + sub * 2], lo);
        __stcs(&op[(rbase + rr) * 16 + sub * 2 + 1], hi);
    }
}

// ---------------------------------------------------------------------------
extern "C" void kernel_launch(void* const* d_in, const int* in_sizes, int n_in,
                              void* d_out, int out_size) {
    const float* x      = (const float*)d_in[0];
    const float* conv_w = (const float*)d_in[1];
    const float* fc1_w  = (const float*)d_in[2];
    const float* fc1_b  = (const float*)d_in[3];
    const float* fc2_w  = (const float*)d_in[4];
    const float* fc2_b  = (const float*)d_in[5];
    float* out = (float*)d_out;

    const int B = in_sizes[0] / (C_CH * HW);   // 32

    gap_kernel<<<B * C_CH, 256>>>(x);
    attn_kernel<<<B, 256>>>(fc1_w, fc1_b, fc2_w, fc2_b);
    conv_kernel<<<B * C_CH / 2, 256>>>(x, conv_w, out);
}

// round 14
// speedup vs baseline: 2.4778x; 1.0542x over previous
#include <cuda_runtime.h>

#define C_CH   256
#define K_KERN 4
#define HID    64
#define HW     4096
#define B_MAX  32

__device__ float g_gap[B_MAX * C_CH];
__device__ float g_attn[B_MAX * K_KERN];

// ---------------------------------------------------------------------------
// Kernel 1: global average pool per (b,c) plane. One block per plane.
// (Proven form — unchanged from the 80.6us baseline.)
// ---------------------------------------------------------------------------
__global__ void __launch_bounds__(256) gap_kernel(const float* __restrict__ x) {
    const int bc = blockIdx.x;
    const float4* __restrict__ p = (const float4*)(x + (size_t)bc * HW);
    float s = 0.f;
#pragma unroll
    for (int i = 0; i < 4; i++) {
        float4 v = __ldg(&p[threadIdx.x + i * 256]);
        s += (v.x + v.y) + (v.z + v.w);
    }
#pragma unroll
    for (int o = 16; o > 0; o >>= 1) s += __shfl_down_sync(0xffffffffu, s, o);
    __shared__ float ws[8];
    const int lane = threadIdx.x & 31, w = threadIdx.x >> 5;
    if (lane == 0) ws[w] = s;
    __syncthreads();
    if (threadIdx.x == 0) {
        float t = 0.f;
#pragma unroll
        for (int i = 0; i < 8; i++) t += ws[i];
        g_gap[bc] = t * (1.0f / (float)HW);
    }
}

// ---------------------------------------------------------------------------
// Kernel 2: fc1 -> relu -> fc2 -> softmax. One block per batch. (unchanged)
// ---------------------------------------------------------------------------
__global__ void __launch_bounds__(256) attn_kernel(const float* __restrict__ fc1_w,
                                                   const float* __restrict__ fc1_b,
                                                   const float* __restrict__ fc2_w,
                                                   const float* __restrict__ fc2_b) {
    const int b = blockIdx.x;
    __shared__ float g[C_CH];
    __shared__ float h[HID];
    __shared__ float lg[K_KERN];

    g[threadIdx.x] = g_gap[b * C_CH + threadIdx.x];
    __syncthreads();

    if (threadIdx.x < HID) {
        const float* __restrict__ wr = fc1_w + threadIdx.x * C_CH;
        float acc = fc1_b[threadIdx.x];
#pragma unroll 8
        for (int c = 0; c < C_CH; c++) acc = fmaf(g[c], wr[c], acc);
        h[threadIdx.x] = fmaxf(acc, 0.f);
    }
    __syncthreads();

    if (threadIdx.x < K_KERN) {
        const float* __restrict__ wr = fc2_w + threadIdx.x * HID;
        float acc = fc2_b[threadIdx.x];
#pragma unroll 8
        for (int j = 0; j < HID; j++) acc = fmaf(h[j], wr[j], acc);
        lg[threadIdx.x] = acc;
    }
    __syncthreads();

    if (threadIdx.x == 0) {
        float m = lg[0];
#pragma unroll
        for (int k = 1; k < K_KERN; k++) m = fmaxf(m, lg[k]);
        float e[K_KERN], s = 0.f;
#pragma unroll
        for (int k = 0; k < K_KERN; k++) { e[k] = expf(lg[k] - m); s += e[k]; }
        const float inv = 1.0f / s;
#pragma unroll
        for (int k = 0; k < K_KERN; k++) g_attn[b * K_KERN + k] = e[k] * inv;
    }
}

// ---------------------------------------------------------------------------
// Kernel 3: depthwise 3x3, effective filter w_eff = sum_k attn[b,k]*w[k,c].
// 16-lane float4 row scheme (proven), but strip = 16 rows per half-warp:
// read amplification 18/16 = 1.125x (was 10/8 = 1.25x). 16 half-warps per
// 256-thread block -> 4 planes per block, 2048 blocks (~2 waves).
// No smem / no syncthreads; width-16 shuffle halo; evict-first stores.
// Reversed plane order: consume gap-resident L2 tail first.
// ---------------------------------------------------------------------------
__device__ __forceinline__ void load_row6(const float4* __restrict__ xp,
                                          int row, int sub, float* d) {
    float4 v;
    if ((unsigned)row < 64u) v = __ldg(&xp[row * 16 + sub]);
    else                     v = make_float4(0.f, 0.f, 0.f, 0.f);
    float l = __shfl_up_sync(0xffffffffu, v.w, 1, 16);
    float r = __shfl_down_sync(0xffffffffu, v.x, 1, 16);
    if (sub == 0)  l = 0.f;
    if (sub == 15) r = 0.f;
    d[0] = l; d[1] = v.x; d[2] = v.y; d[3] = v.z; d[4] = v.w; d[5] = r;
}

__global__ void __launch_bounds__(256) conv_kernel(const float* __restrict__ x,
                                                   const float* __restrict__ conv_w,
                                                   float* __restrict__ out) {
    const int tid  = threadIdx.x;
    const int lane = tid & 31;
    const int warp = tid >> 5;
    const int sub  = lane & 15;              // column group (0..15)
    const int gs   = warp * 2 + (lane >> 4); // half-warp id 0..15
    const int plane_local = gs >> 2;         // 0..3
    const int strip = gs & 3;                // 0..3 -> rows [strip*16, strip*16+16)

    const int grp = gridDim.x - 1 - blockIdx.x;   // reversed order
    const int bc = grp * 4 + plane_local;
    const int b = bc >> 8;
    const int c = bc & 255;

    const float a0 = g_attn[b * 4 + 0];
    const float a1 = g_attn[b * 4 + 1];
    const float a2 = g_attn[b * 4 + 2];
    const float a3 = g_attn[b * 4 + 3];
    float w[9];
    const float* __restrict__ w0 = conv_w + (size_t)0 * C_CH * 9 + c * 9;
    const float* __restrict__ w1 = conv_w + (size_t)1 * C_CH * 9 + c * 9;
    const float* __restrict__ w2 = conv_w + (size_t)2 * C_CH * 9 + c * 9;
    const float* __restrict__ w3 = conv_w + (size_t)3 * C_CH * 9 + c * 9;
#pragma unroll
    for (int i = 0; i < 9; i++)
        w[i] = fmaf(a0, __ldg(&w0[i]),
               fmaf(a1, __ldg(&w1[i]),
               fmaf(a2, __ldg(&w2[i]), a3 * __ldg(&w3[i]))));

    const float4* __restrict__ xp = (const float4*)(x + (size_t)bc * HW);
    float4* __restrict__ op = (float4*)(out + (size_t)bc * HW);

    const int rbase = strip * 16;

    float rb[3][6];
    load_row6(xp, rbase - 1, sub, rb[0]);
    load_row6(xp, rbase,     sub, rb[1]);

#pragma unroll
    for (int rr = 0; rr < 16; rr++) {
        const int i0 = rr % 3;
        const int i1 = (rr + 1) % 3;
        const int i2 = (rr + 2) % 3;
        load_row6(xp, rbase + rr + 1, sub, rb[i2]);

        float4 o;
        float* ov = (float*)&o;
#pragma unroll
        for (int i = 0; i < 4; i++) {
            float acc;
            acc = rb[i0][i]     * w[0];
            acc = fmaf(rb[i0][i + 1], w[1], acc);
            acc = fmaf(rb[i0][i + 2], w[2], acc);
            acc = fmaf(rb[i1][i],     w[3], acc);
            acc = fmaf(rb[i1][i + 1], w[4], acc);
            acc = fmaf(rb[i1][i + 2], w[5], acc);
            acc = fmaf(rb[i2][i],     w[6], acc);
            acc = fmaf(rb[i2][i + 1], w[7], acc);
            acc = fmaf(rb[i2][i + 2], w[8], acc);
            ov[i] = acc;
        }
        __stcs(&op[(rbase + rr) * 16 + sub], o);
    }
}

// ---------------------------------------------------------------------------
extern "C" void kernel_launch(void* const* d_in, const int* in_sizes, int n_in,
                              void* d_out, int out_size) {
    const float* x      = (const float*)d_in[0];
    const float* conv_w = (const float*)d_in[1];
    const float* fc1_w  = (const float*)d_in[2];
    const float* fc1_b  = (const float*)d_in[3];
    const float* fc2_w  = (const float*)d_in[4];
    const float* fc2_b  = (const float*)d_in[5];
    float* out = (float*)d_out;

    const int B = in_sizes[0] / (C_CH * HW);   // 32

    gap_kernel<<<B * C_CH, 256>>>(x);
    attn_kernel<<<B, 256>>>(fc1_w, fc1_b, fc2_w, fc2_b);
    conv_kernel<<<B * C_CH / 4, 256>>>(x, conv_w, out);
}